// round 14
// baseline (speedup 1.0000x reference)
#include <cuda_runtime.h>
#include <cuda_fp16.h>
#include <cstdint>
#include <math.h>

#define NN 50000
#define HH 128
#define EE 600000
#define GG 256
#define OUTD 64
#define NITER 5
#define GAMMA 0.1f
#define EPS 0.1f
#define SLOPE 0.01f
#define SCAN_NBLK 98   /* ceil(50000/512) */

// ---------------- device scratch (static, allocation-free) ----------------
__device__ float g_x[NN * HH];
__device__ __half g_xh[NN * HH];               // fp16 x (GEMM A operand)
__device__ __half g_nh[NN * HH];               // neigh, fp16 (gathered)
__device__ float g_conv[NN * HH];
__device__ __half g_Wh[256 * 128];
__device__ int   g_counts[NN];
__device__ int   g_rowptr[NN + 1];
__device__ int   g_fillptr[NN];
__device__ int   g_blocksums[SCAN_NBLK];
__device__ int   g_srcsorted[EE];
__device__ int   g_gstart[GG + 1];
__device__ float g_pooled[GG * 384];
__device__ float g_h[GG * 192];

__device__ __forceinline__ uint32_t smem_u32(const void* p) {
    uint32_t a;
    asm("{ .reg .u64 t; cvta.to.shared.u64 t, %1; cvt.u32.u64 %0, t; }" : "=r"(a) : "l"(p));
    return a;
}

__device__ __forceinline__ float tanh_fast(float x) {
    float r;
    asm("tanh.approx.f32 %0, %1;" : "=f"(r) : "f"(x));
    return r;
}

// ---------------- prep kernels ----------------
__global__ void wprep_kernel(const float* __restrict__ W, const float* __restrict__ lin_w) {
    int n = blockIdx.x;
    int k = threadIdx.x;
    float v;
    if (n < 128) {
        v = lin_w[n * HH + k];
    } else {
        int np = n - 128;
        v = W[np * HH + k] - W[k * HH + np] - (np == k ? GAMMA : 0.0f);
    }
    g_Wh[n * 128 + k] = __float2half_rn(v);
}

__global__ void copy_x_kernel(const float* __restrict__ xin) {
    int i = blockIdx.x * blockDim.x + threadIdx.x;
    if (i < NN) g_counts[i] = 0;
    if (i < NN * HH / 4) {
        float4 f = reinterpret_cast<const float4*>(xin)[i];
        reinterpret_cast<float4*>(g_x)[i] = f;
        __half2 h0 = __floats2half2_rn(f.x, f.y);
        __half2 h1 = __floats2half2_rn(f.z, f.w);
        reinterpret_cast<uint2*>(g_xh)[i] =
            make_uint2(*reinterpret_cast<uint32_t*>(&h0), *reinterpret_cast<uint32_t*>(&h1));
    }
}

__global__ void hist_kernel(const int* __restrict__ ei) {
    int e = blockIdx.x * blockDim.x + threadIdx.x;
    if (e < EE) {
        int dst = ei[EE + e];
        atomicAdd(&g_counts[dst], 1);
    }
}

// ---- multi-block scan, 3 phases ----
__global__ void scan_local_kernel() {
    __shared__ int ws[16];
    int i = blockIdx.x * 512 + threadIdx.x;
    int lane = threadIdx.x & 31;
    int wid = threadIdx.x >> 5;
    int v = (i < NN) ? g_counts[i] : 0;
    int inc = v;
    #pragma unroll
    for (int off = 1; off < 32; off <<= 1) {
        int o = __shfl_up_sync(0xffffffffu, inc, off);
        if (lane >= off) inc += o;
    }
    if (lane == 31) ws[wid] = inc;
    __syncthreads();
    if (wid == 0) {
        int w = (lane < 16) ? ws[lane] : 0;
        int wi = w;
        #pragma unroll
        for (int off = 1; off < 32; off <<= 1) {
            int o = __shfl_up_sync(0xffffffffu, wi, off);
            if (lane >= off) wi += o;
        }
        if (lane < 16) ws[lane] = wi - w;
    }
    __syncthreads();
    int exc = ws[wid] + inc - v;
    if (i < NN) g_rowptr[i] = exc;
    if (threadIdx.x == 511) g_blocksums[blockIdx.x] = exc + v;
}

__global__ void scan_tops_kernel() {
    __shared__ int ws[4];
    int t = threadIdx.x;
    int lane = t & 31;
    int wid = t >> 5;
    int v = (t < SCAN_NBLK) ? g_blocksums[t] : 0;
    int inc = v;
    #pragma unroll
    for (int off = 1; off < 32; off <<= 1) {
        int o = __shfl_up_sync(0xffffffffu, inc, off);
        if (lane >= off) inc += o;
    }
    if (lane == 31) ws[wid] = inc;
    __syncthreads();
    if (t == 0) {
        int r = 0;
        #pragma unroll
        for (int q = 0; q < 4; q++) { int x = ws[q]; ws[q] = r; r += x; }
    }
    __syncthreads();
    if (t < SCAN_NBLK) g_blocksums[t] = ws[wid] + inc - v;
}

__global__ void scan_add_kernel() {
    int i = blockIdx.x * 512 + threadIdx.x;
    if (i < NN) {
        int r = g_rowptr[i] + g_blocksums[blockIdx.x];
        g_rowptr[i] = r;
        g_fillptr[i] = r;
    }
    if (i == 0) g_rowptr[NN] = EE;
}

__global__ void fill_kernel(const int* __restrict__ ei) {
    int e = blockIdx.x * blockDim.x + threadIdx.x;
    if (e < EE) {
        int src = ei[e];
        int dst = ei[EE + e];
        int pos = atomicAdd(&g_fillptr[dst], 1);
        g_srcsorted[pos] = src;
    }
}

// ---------------- HMMA GEMM (pure fp16, 1-term, K-split pipeline) ----------------
#define SROWB 272
#define OFF_A 0
#define OFF_B 34816                  // 128*272
#define SM_TOTAL 52224               // + 64*272

#define LDM_X4(d, addr) \
    asm volatile("ldmatrix.sync.aligned.m8n8.x4.shared.b16 {%0,%1,%2,%3}, [%4];" \
        : "=r"((d)[0]), "=r"((d)[1]), "=r"((d)[2]), "=r"((d)[3]) : "r"(addr))

#define MMA_F16(c, a, b) \
    asm volatile("mma.sync.aligned.m16n8k16.row.col.f32.f16.f16.f32 " \
        "{%0,%1,%2,%3}, {%4,%5,%6,%7}, {%8,%9}, {%0,%1,%2,%3};" \
        : "+f"((c)[0]), "+f"((c)[1]), "+f"((c)[2]), "+f"((c)[3]) \
        : "r"((a)[0]), "r"((a)[1]), "r"((a)[2]), "r"((a)[3]), "r"((b)[0]), "r"((b)[1]))

__device__ __forceinline__ void cp16(uint32_t dst, const void* src, uint32_t srcsize) {
    asm volatile("cp.async.ca.shared.global [%0], [%1], 16, %2;"
                 :: "r"(dst), "l"(src), "r"(srcsize) : "memory");
}

__global__ __launch_bounds__(256, 4) void gemm_hmma_kernel() {
    extern __shared__ char sm[];
    uint32_t sb = smem_u32(sm);
    int tid = threadIdx.x;
    int warp = tid >> 5;
    int lane = tid & 31;
    int rowbase = blockIdx.x * 128;
    int nbase = blockIdx.y * 64;

    #pragma unroll
    for (int h = 0; h < 2; h++) {
        #pragma unroll
        for (int p = 0; p < 4; p++) {
            int idx = tid + p * 256;
            int row = idx >> 3;
            int cc = (idx & 7) + h * 8;
            int gr = rowbase + row;
            uint32_t ok = (gr < NN) ? 16u : 0u;
            int grc = (gr < NN) ? gr : 0;
            uint32_t doff = (uint32_t)(row * SROWB + cc * 16);
            cp16(sb + OFF_A + doff, &g_xh[(size_t)grc * 128 + cc * 8], ok);
        }
        #pragma unroll
        for (int p = 0; p < 2; p++) {
            int idx = tid + p * 256;
            int row = idx >> 3;
            int cc = (idx & 7) + h * 8;
            uint32_t doff = (uint32_t)(row * SROWB + cc * 16);
            cp16(sb + OFF_B + doff, &g_Wh[(size_t)(nbase + row) * 128 + cc * 8], 16u);
        }
        asm volatile("cp.async.commit_group;");
    }

    int mrow = (warp & 3) * 32;
    int ncol = (warp >> 2) * 32;
    int g = lane >> 2;
    int tig = lane & 3;

    uint32_t aoffA = (uint32_t)((mrow + (lane & 15)) * SROWB + (lane >> 4) * 16);
    int bm = lane >> 3;
    uint32_t aoffB = (uint32_t)((ncol + ((bm >> 1) << 3) + (lane & 7)) * SROWB + (bm & 1) * 16);

    float acc[2][4][4];
    #pragma unroll
    for (int mt = 0; mt < 2; mt++)
        #pragma unroll
        for (int nt = 0; nt < 4; nt++)
            #pragma unroll
            for (int q = 0; q < 4; q++) acc[mt][nt][q] = 0.f;

    asm volatile("cp.async.wait_group 1;");
    __syncthreads();

    #pragma unroll
    for (int ks = 0; ks < 8; ks++) {
        if (ks == 4) {
            asm volatile("cp.async.wait_group 0;");
            __syncthreads();
        }
        uint32_t kb = (uint32_t)(ks * 32);
        uint32_t aa[2][4], bb[2][4];
        #pragma unroll
        for (int mt = 0; mt < 2; mt++) {
            LDM_X4(aa[mt], sb + OFF_A + aoffA + mt * 16 * SROWB + kb);
        }
        #pragma unroll
        for (int pr = 0; pr < 2; pr++) {
            LDM_X4(bb[pr], sb + OFF_B + aoffB + pr * 16 * SROWB + kb);
        }
        #pragma unroll
        for (int mt = 0; mt < 2; mt++) {
            #pragma unroll
            for (int nt = 0; nt < 4; nt++) {
                uint32_t bh[2] = {bb[nt >> 1][(nt & 1) * 2], bb[nt >> 1][(nt & 1) * 2 + 1]};
                MMA_F16(acc[mt][nt], aa[mt], bh);
            }
        }
    }

    bool is_neigh = (nbase < 128);
    int cb = is_neigh ? nbase : (nbase - 128);
    #pragma unroll
    for (int mt = 0; mt < 2; mt++) {
        int r0 = rowbase + mrow + mt * 16 + g;
        int r1 = r0 + 8;
        #pragma unroll
        for (int nt = 0; nt < 4; nt++) {
            int col = cb + ncol + nt * 8 + 2 * tig;
            if (is_neigh) {
                __half2 p0 = __floats2half2_rn(acc[mt][nt][0], acc[mt][nt][1]);
                __half2 p1 = __floats2half2_rn(acc[mt][nt][2], acc[mt][nt][3]);
                if (r0 < NN) *reinterpret_cast<__half2*>(&g_nh[(size_t)r0 * 128 + col]) = p0;
                if (r1 < NN) *reinterpret_cast<__half2*>(&g_nh[(size_t)r1 * 128 + col]) = p1;
            } else {
                if (r0 < NN) *reinterpret_cast<float2*>(&g_conv[(size_t)r0 * 128 + col]) =
                    make_float2(acc[mt][nt][0], acc[mt][nt][1]);
                if (r1 < NN) *reinterpret_cast<float2*>(&g_conv[(size_t)r1 * 128 + col]) =
                    make_float2(acc[mt][nt][2], acc[mt][nt][3]);
            }
        }
    }
}

// ---------------- fused aggregate + conv + tanh + x update (warp per node) ----------------
// Packed fp16 accumulation: 2 HADD2 per edge-lane (was 2 CVT + 4 FADD).
// 4 independent half2-pair accumulators; fp32 combine at the end.
__global__ __launch_bounds__(256) void agg_update_kernel(const float* __restrict__ bias) {
    int node = (blockIdx.x * blockDim.x + threadIdx.x) >> 5;
    int lane = threadIdx.x & 31;
    if (node >= NN) return;
    int s = g_rowptr[node];
    int e = g_rowptr[node + 1];

    float4 cv = *reinterpret_cast<const float4*>(&g_conv[(size_t)node * 128 + lane * 4]);
    float4 xr = *reinterpret_cast<const float4*>(&g_x[(size_t)node * HH + lane * 4]);
    float4 bv = *reinterpret_cast<const float4*>(&bias[lane * 4]);

    __half2 z2 = __floats2half2_rn(0.f, 0.f);
    __half2 a0x = z2, a0y = z2, a1x = z2, a1y = z2;
    __half2 a2x = z2, a2y = z2, a3x = z2, a3y = z2;

    int p = s;
    for (; p + 3 < e; p += 4) {
        int i0 = g_srcsorted[p + 0];
        int i1 = g_srcsorted[p + 1];
        int i2 = g_srcsorted[p + 2];
        int i3 = g_srcsorted[p + 3];
        uint2 u0 = *reinterpret_cast<const uint2*>(&g_nh[(size_t)i0 * 128 + lane * 4]);
        uint2 u1 = *reinterpret_cast<const uint2*>(&g_nh[(size_t)i1 * 128 + lane * 4]);
        uint2 u2 = *reinterpret_cast<const uint2*>(&g_nh[(size_t)i2 * 128 + lane * 4]);
        uint2 u3 = *reinterpret_cast<const uint2*>(&g_nh[(size_t)i3 * 128 + lane * 4]);
        a0x = __hadd2(a0x, *reinterpret_cast<__half2*>(&u0.x));
        a0y = __hadd2(a0y, *reinterpret_cast<__half2*>(&u0.y));
        a1x = __hadd2(a1x, *reinterpret_cast<__half2*>(&u1.x));
        a1y = __hadd2(a1y, *reinterpret_cast<__half2*>(&u1.y));
        a2x = __hadd2(a2x, *reinterpret_cast<__half2*>(&u2.x));
        a2y = __hadd2(a2y, *reinterpret_cast<__half2*>(&u2.y));
        a3x = __hadd2(a3x, *reinterpret_cast<__half2*>(&u3.x));
        a3y = __hadd2(a3y, *reinterpret_cast<__half2*>(&u3.y));
    }
    for (; p < e; p++) {
        int i0 = g_srcsorted[p];
        uint2 u0 = *reinterpret_cast<const uint2*>(&g_nh[(size_t)i0 * 128 + lane * 4]);
        a0x = __hadd2(a0x, *reinterpret_cast<__half2*>(&u0.x));
        a0y = __hadd2(a0y, *reinterpret_cast<__half2*>(&u0.y));
    }

    // fp32 combine of the 4 accumulator pairs
    float2 f0, f1, f2, f3;
    float4 a;
    f0 = __half22float2(a0x); f1 = __half22float2(a1x);
    f2 = __half22float2(a2x); f3 = __half22float2(a3x);
    a.x = (f0.x + f1.x) + (f2.x + f3.x);
    a.y = (f0.y + f1.y) + (f2.y + f3.y);
    f0 = __half22float2(a0y); f1 = __half22float2(a1y);
    f2 = __half22float2(a2y); f3 = __half22float2(a3y);
    a.z = (f0.x + f1.x) + (f2.x + f3.x);
    a.w = (f0.y + f1.y) + (f2.y + f3.y);

    xr.x += EPS * tanh_fast(cv.x + a.x + bv.x);
    xr.y += EPS * tanh_fast(cv.y + a.y + bv.y);
    xr.z += EPS * tanh_fast(cv.z + a.z + bv.z);
    xr.w += EPS * tanh_fast(cv.w + a.w + bv.w);
    *reinterpret_cast<float4*>(&g_x[(size_t)node * HH + lane * 4]) = xr;

    __half2 h0 = __floats2half2_rn(xr.x, xr.y);
    __half2 h1 = __floats2half2_rn(xr.z, xr.w);
    *reinterpret_cast<uint2*>(&g_xh[(size_t)node * HH + lane * 4]) =
        make_uint2(*reinterpret_cast<uint32_t*>(&h0), *reinterpret_cast<uint32_t*>(&h1));
}

// ---------------- pooling ----------------
__global__ void gstart_kernel(const int* __restrict__ batch) {
    int g = blockIdx.x * blockDim.x + threadIdx.x;
    if (g > GG) return;
    int lo = 0, hi = NN;
    while (lo < hi) {
        int mid = (lo + hi) >> 1;
        if (batch[mid] < g) lo = mid + 1; else hi = mid;
    }
    g_gstart[g] = lo;
}

__global__ void pool_kernel() {
    int g = blockIdx.x;
    int c = threadIdx.x;
    int s = g_gstart[g], e = g_gstart[g + 1];
    float sum = 0.f;
    float mx = -3.402823466e+38f;
    for (int i = s; i < e; i++) {
        float v = g_x[(size_t)i * HH + c];
        sum += v;
        mx = fmaxf(mx, v);
    }
    int cnt = e - s;
    g_pooled[g * 384 + c] = sum;
    g_pooled[g * 384 + 128 + c] = (cnt > 0) ? mx : 0.f;
    g_pooled[g * 384 + 256 + c] = sum / fmaxf((float)cnt, 1.0f);
}

// ---------------- MLP head ----------------
__global__ void mlp1_kernel(const float* __restrict__ l1w, const float* __restrict__ l1b) {
    __shared__ float prow[384];
    int g = blockIdx.x;
    int j = threadIdx.x;
    for (int idx = j; idx < 384; idx += 192) prow[idx] = g_pooled[g * 384 + idx];
    __syncthreads();
    float acc = l1b[j];
    const float* wrow = &l1w[j * 384];
    #pragma unroll 8
    for (int k = 0; k < 384; k++) acc += prow[k] * wrow[k];
    g_h[g * 192 + j] = (acc > 0.f) ? acc : SLOPE * acc;
}

__global__ void mlp2_kernel(const float* __restrict__ l2w, const float* __restrict__ l2b,
                            float* __restrict__ out) {
    __shared__ float hrow[192];
    int g = blockIdx.x;
    int j = threadIdx.x;
    for (int idx = j; idx < 192; idx += 64) hrow[idx] = g_h[g * 192 + idx];
    __syncthreads();
    float acc = l2b[j];
    const float* wrow = &l2w[j * 192];
    #pragma unroll 8
    for (int k = 0; k < 192; k++) acc += hrow[k] * wrow[k];
    out[g * OUTD + j] = (acc > 0.f) ? acc : SLOPE * acc;
}

// ---------------- launch ----------------
extern "C" void kernel_launch(void* const* d_in, const int* in_sizes, int n_in,
                              void* d_out, int out_size) {
    const float* x_in  = (const float*)d_in[0];
    const int*   ei    = (const int*)d_in[1];
    const int*   batch = (const int*)d_in[2];
    const float* W     = (const float*)d_in[3];
    const float* bias  = (const float*)d_in[4];
    const float* lin_w = (const float*)d_in[5];
    const float* l1w   = (const float*)d_in[6];
    const float* l1b   = (const float*)d_in[7];
    const float* l2w   = (const float*)d_in[8];
    const float* l2b   = (const float*)d_in[9];
    float* out = (float*)d_out;

    cudaFuncSetAttribute(gemm_hmma_kernel, cudaFuncAttributeMaxDynamicSharedMemorySize, SM_TOTAL);

    dim3 ggrid((NN + 127) / 128, 4);

    // prep (gemm#1 is launch #4 -> profiled)
    wprep_kernel<<<256, 128>>>(W, lin_w);
    copy_x_kernel<<<(NN * HH / 4 + 255) / 256, 256>>>(x_in);
    hist_kernel<<<(EE + 255) / 256, 256>>>(ei);
    gemm_hmma_kernel<<<ggrid, 256, SM_TOTAL>>>();
    scan_local_kernel<<<SCAN_NBLK, 512>>>();
    scan_tops_kernel<<<1, 128>>>();
    scan_add_kernel<<<SCAN_NBLK, 512>>>();
    fill_kernel<<<(EE + 255) / 256, 256>>>(ei);
    agg_update_kernel<<<(NN * 32 + 255) / 256, 256>>>(bias);

    for (int it = 1; it < NITER; it++) {
        gemm_hmma_kernel<<<ggrid, 256, SM_TOTAL>>>();
        agg_update_kernel<<<(NN * 32 + 255) / 256, 256>>>(bias);
    }

    gstart_kernel<<<1, 512>>>(batch);
    pool_kernel<<<GG, HH>>>();
    mlp1_kernel<<<GG, 192>>>(l1w, l1b);
    mlp2_kernel<<<GG, OUTD>>>(l2w, l2b, out);
}

// round 15
// speedup vs baseline: 1.0364x; 1.0364x over previous
#include <cuda_runtime.h>
#include <cuda_fp16.h>
#include <cstdint>
#include <math.h>

#define NN 50000
#define HH 128
#define EE 600000
#define GG 256
#define OUTD 64
#define NITER 5
#define GAMMA 0.1f
#define EPS 0.1f
#define SLOPE 0.01f
#define SCAN_NBLK 98   /* ceil(50000/512) */

// ---------------- device scratch (static, allocation-free) ----------------
__device__ float g_x[NN * HH];
__device__ __half g_xh[NN * HH];               // fp16 x (GEMM A operand)
__device__ __half g_nh[NN * HH];               // neigh, fp16 (gathered)
__device__ float g_conv[NN * HH];
__device__ __half g_Wh[256 * 128];
__device__ int   g_counts[NN];
__device__ int   g_rowptr[NN + 1];
__device__ int   g_fillptr[NN];
__device__ int   g_blocksums[SCAN_NBLK];
__device__ int   g_srcsorted[EE];
__device__ int   g_gstart[GG + 1];
__device__ float g_pooled[GG * 384];
__device__ float g_h[GG * 192];

__device__ __forceinline__ uint32_t smem_u32(const void* p) {
    uint32_t a;
    asm("{ .reg .u64 t; cvta.to.shared.u64 t, %1; cvt.u32.u64 %0, t; }" : "=r"(a) : "l"(p));
    return a;
}

__device__ __forceinline__ float tanh_fast(float x) {
    float r;
    asm("tanh.approx.f32 %0, %1;" : "=f"(r) : "f"(x));
    return r;
}

// ---------------- prep kernels ----------------
__global__ void wprep_kernel(const float* __restrict__ W, const float* __restrict__ lin_w) {
    int n = blockIdx.x;
    int k = threadIdx.x;
    float v;
    if (n < 128) {
        v = lin_w[n * HH + k];
    } else {
        int np = n - 128;
        v = W[np * HH + k] - W[k * HH + np] - (np == k ? GAMMA : 0.0f);
    }
    g_Wh[n * 128 + k] = __float2half_rn(v);
}

__global__ void copy_x_kernel(const float* __restrict__ xin) {
    int i = blockIdx.x * blockDim.x + threadIdx.x;
    if (i < NN) g_counts[i] = 0;
    if (i < NN * HH / 4) {
        float4 f = reinterpret_cast<const float4*>(xin)[i];
        reinterpret_cast<float4*>(g_x)[i] = f;
        __half2 h0 = __floats2half2_rn(f.x, f.y);
        __half2 h1 = __floats2half2_rn(f.z, f.w);
        reinterpret_cast<uint2*>(g_xh)[i] =
            make_uint2(*reinterpret_cast<uint32_t*>(&h0), *reinterpret_cast<uint32_t*>(&h1));
    }
}

__global__ void hist_kernel(const int* __restrict__ ei) {
    int e = blockIdx.x * blockDim.x + threadIdx.x;
    if (e < EE) {
        int dst = ei[EE + e];
        atomicAdd(&g_counts[dst], 1);
    }
}

// ---- multi-block scan, 3 phases ----
__global__ void scan_local_kernel() {
    __shared__ int ws[16];
    int i = blockIdx.x * 512 + threadIdx.x;
    int lane = threadIdx.x & 31;
    int wid = threadIdx.x >> 5;
    int v = (i < NN) ? g_counts[i] : 0;
    int inc = v;
    #pragma unroll
    for (int off = 1; off < 32; off <<= 1) {
        int o = __shfl_up_sync(0xffffffffu, inc, off);
        if (lane >= off) inc += o;
    }
    if (lane == 31) ws[wid] = inc;
    __syncthreads();
    if (wid == 0) {
        int w = (lane < 16) ? ws[lane] : 0;
        int wi = w;
        #pragma unroll
        for (int off = 1; off < 32; off <<= 1) {
            int o = __shfl_up_sync(0xffffffffu, wi, off);
            if (lane >= off) wi += o;
        }
        if (lane < 16) ws[lane] = wi - w;
    }
    __syncthreads();
    int exc = ws[wid] + inc - v;
    if (i < NN) g_rowptr[i] = exc;
    if (threadIdx.x == 511) g_blocksums[blockIdx.x] = exc + v;
}

__global__ void scan_tops_kernel() {
    __shared__ int ws[4];
    int t = threadIdx.x;
    int lane = t & 31;
    int wid = t >> 5;
    int v = (t < SCAN_NBLK) ? g_blocksums[t] : 0;
    int inc = v;
    #pragma unroll
    for (int off = 1; off < 32; off <<= 1) {
        int o = __shfl_up_sync(0xffffffffu, inc, off);
        if (lane >= off) inc += o;
    }
    if (lane == 31) ws[wid] = inc;
    __syncthreads();
    if (t == 0) {
        int r = 0;
        #pragma unroll
        for (int q = 0; q < 4; q++) { int x = ws[q]; ws[q] = r; r += x; }
    }
    __syncthreads();
    if (t < SCAN_NBLK) g_blocksums[t] = ws[wid] + inc - v;
}

__global__ void scan_add_kernel() {
    int i = blockIdx.x * 512 + threadIdx.x;
    if (i < NN) {
        int r = g_rowptr[i] + g_blocksums[blockIdx.x];
        g_rowptr[i] = r;
        g_fillptr[i] = r;
    }
    if (i == 0) g_rowptr[NN] = EE;
}

__global__ void fill_kernel(const int* __restrict__ ei) {
    int e = blockIdx.x * blockDim.x + threadIdx.x;
    if (e < EE) {
        int src = ei[e];
        int dst = ei[EE + e];
        int pos = atomicAdd(&g_fillptr[dst], 1);
        g_srcsorted[pos] = src;
    }
}

// ---------------- HMMA GEMM (pure fp16, 1-term, M128xN128, warp 32x64) ----------------
// CTA tile M=128, N=128, K=128 (two 64-col cp.async chunks). 8 warps (4M x 2N).
// LDSM/MMA = 0.375 (down from 0.5). grid (391, 2). SMEM 68KB -> 2 CTAs/SM.
#define SROWB 272
#define OFF_A 0
#define OFF_B 34816                  // 128*272
#define SM_TOTAL 69632               // + 128*272

#define LDM_X4(d, addr) \
    asm volatile("ldmatrix.sync.aligned.m8n8.x4.shared.b16 {%0,%1,%2,%3}, [%4];" \
        : "=r"((d)[0]), "=r"((d)[1]), "=r"((d)[2]), "=r"((d)[3]) : "r"(addr))

#define MMA_F16(c, a, b) \
    asm volatile("mma.sync.aligned.m16n8k16.row.col.f32.f16.f16.f32 " \
        "{%0,%1,%2,%3}, {%4,%5,%6,%7}, {%8,%9}, {%0,%1,%2,%3};" \
        : "+f"((c)[0]), "+f"((c)[1]), "+f"((c)[2]), "+f"((c)[3]) \
        : "r"((a)[0]), "r"((a)[1]), "r"((a)[2]), "r"((a)[3]), "r"((b)[0]), "r"((b)[1]))

__device__ __forceinline__ void cp16(uint32_t dst, const void* src, uint32_t srcsize) {
    asm volatile("cp.async.ca.shared.global [%0], [%1], 16, %2;"
                 :: "r"(dst), "l"(src), "r"(srcsize) : "memory");
}

__global__ __launch_bounds__(256, 2) void gemm_hmma_kernel() {
    extern __shared__ char sm[];
    uint32_t sb = smem_u32(sm);
    int tid = threadIdx.x;
    int warp = tid >> 5;
    int lane = tid & 31;
    int rowbase = blockIdx.x * 128;
    int nbase = blockIdx.y * 128;

    // ---- K-split loads: chunk h covers fp16 cols [h*64, h*64+64) ----
    #pragma unroll
    for (int h = 0; h < 2; h++) {
        // A: 128 rows x 8 (16B) segs per chunk
        #pragma unroll
        for (int p = 0; p < 4; p++) {
            int idx = tid + p * 256;           // 0..1023
            int row = idx >> 3;                // 0..127
            int cc = (idx & 7) + h * 8;        // 16B-seg 0..15
            int gr = rowbase + row;
            uint32_t ok = (gr < NN) ? 16u : 0u;
            int grc = (gr < NN) ? gr : 0;
            uint32_t doff = (uint32_t)(row * SROWB + cc * 16);
            cp16(sb + OFF_A + doff, &g_xh[(size_t)grc * 128 + cc * 8], ok);
        }
        // B: 128 rows x 8 segs per chunk
        #pragma unroll
        for (int p = 0; p < 4; p++) {
            int idx = tid + p * 256;           // 0..1023
            int row = idx >> 3;                // 0..127
            int cc = (idx & 7) + h * 8;
            uint32_t doff = (uint32_t)(row * SROWB + cc * 16);
            cp16(sb + OFF_B + doff, &g_Wh[(size_t)(nbase + row) * 128 + cc * 8], 16u);
        }
        asm volatile("cp.async.commit_group;");
    }

    int mrow = (warp & 3) * 32;
    int ncol = (warp >> 2) * 64;
    int g = lane >> 2;
    int tig = lane & 3;

    uint32_t aoffA = (uint32_t)((mrow + (lane & 15)) * SROWB + (lane >> 4) * 16);
    int bm = lane >> 3;
    uint32_t aoffB = (uint32_t)((ncol + ((bm >> 1) << 3) + (lane & 7)) * SROWB + (bm & 1) * 16);

    float acc[2][8][4];
    #pragma unroll
    for (int mt = 0; mt < 2; mt++)
        #pragma unroll
        for (int nt = 0; nt < 8; nt++)
            #pragma unroll
            for (int q = 0; q < 4; q++) acc[mt][nt][q] = 0.f;

    asm volatile("cp.async.wait_group 1;");
    __syncthreads();

    #pragma unroll
    for (int ks = 0; ks < 8; ks++) {
        if (ks == 4) {
            asm volatile("cp.async.wait_group 0;");
            __syncthreads();
        }
        uint32_t kb = (uint32_t)(ks * 32);
        uint32_t aa[2][4], bb[4][4];
        #pragma unroll
        for (int mt = 0; mt < 2; mt++) {
            LDM_X4(aa[mt], sb + OFF_A + aoffA + mt * 16 * SROWB + kb);
        }
        #pragma unroll
        for (int pr = 0; pr < 4; pr++) {
            LDM_X4(bb[pr], sb + OFF_B + aoffB + pr * 16 * SROWB + kb);
        }
        #pragma unroll
        for (int mt = 0; mt < 2; mt++) {
            #pragma unroll
            for (int nt = 0; nt < 8; nt++) {
                uint32_t bh[2] = {bb[nt >> 1][(nt & 1) * 2], bb[nt >> 1][(nt & 1) * 2 + 1]};
                MMA_F16(acc[mt][nt], aa[mt], bh);
            }
        }
    }

    bool is_neigh = (blockIdx.y == 0);
    #pragma unroll
    for (int mt = 0; mt < 2; mt++) {
        int r0 = rowbase + mrow + mt * 16 + g;
        int r1 = r0 + 8;
        #pragma unroll
        for (int nt = 0; nt < 8; nt++) {
            int col = ncol + nt * 8 + 2 * tig;
            if (is_neigh) {
                __half2 p0 = __floats2half2_rn(acc[mt][nt][0], acc[mt][nt][1]);
                __half2 p1 = __floats2half2_rn(acc[mt][nt][2], acc[mt][nt][3]);
                if (r0 < NN) *reinterpret_cast<__half2*>(&g_nh[(size_t)r0 * 128 + col]) = p0;
                if (r1 < NN) *reinterpret_cast<__half2*>(&g_nh[(size_t)r1 * 128 + col]) = p1;
            } else {
                if (r0 < NN) *reinterpret_cast<float2*>(&g_conv[(size_t)r0 * 128 + col]) =
                    make_float2(acc[mt][nt][0], acc[mt][nt][1]);
                if (r1 < NN) *reinterpret_cast<float2*>(&g_conv[(size_t)r1 * 128 + col]) =
                    make_float2(acc[mt][nt][2], acc[mt][nt][3]);
            }
        }
    }
}

// ---------------- fused aggregate + conv + tanh + x update (warp per node, R13) ----------------
__global__ __launch_bounds__(256) void agg_update_kernel(const float* __restrict__ bias) {
    int node = (blockIdx.x * blockDim.x + threadIdx.x) >> 5;
    int lane = threadIdx.x & 31;
    if (node >= NN) return;
    int s = g_rowptr[node];
    int e = g_rowptr[node + 1];

    float4 cv = *reinterpret_cast<const float4*>(&g_conv[(size_t)node * 128 + lane * 4]);
    float4 xr = *reinterpret_cast<const float4*>(&g_x[(size_t)node * HH + lane * 4]);
    float4 bv = *reinterpret_cast<const float4*>(&bias[lane * 4]);

    float4 a0 = make_float4(0.f, 0.f, 0.f, 0.f);
    float4 a1 = a0, a2 = a0, a3 = a0;

    int p = s;
    for (; p + 3 < e; p += 4) {
        int i0 = g_srcsorted[p + 0];
        int i1 = g_srcsorted[p + 1];
        int i2 = g_srcsorted[p + 2];
        int i3 = g_srcsorted[p + 3];
        uint2 u0 = *reinterpret_cast<const uint2*>(&g_nh[(size_t)i0 * 128 + lane * 4]);
        uint2 u1 = *reinterpret_cast<const uint2*>(&g_nh[(size_t)i1 * 128 + lane * 4]);
        uint2 u2 = *reinterpret_cast<const uint2*>(&g_nh[(size_t)i2 * 128 + lane * 4]);
        uint2 u3 = *reinterpret_cast<const uint2*>(&g_nh[(size_t)i3 * 128 + lane * 4]);
        float2 f;
        f = __half22float2(*reinterpret_cast<__half2*>(&u0.x)); a0.x += f.x; a0.y += f.y;
        f = __half22float2(*reinterpret_cast<__half2*>(&u0.y)); a0.z += f.x; a0.w += f.y;
        f = __half22float2(*reinterpret_cast<__half2*>(&u1.x)); a1.x += f.x; a1.y += f.y;
        f = __half22float2(*reinterpret_cast<__half2*>(&u1.y)); a1.z += f.x; a1.w += f.y;
        f = __half22float2(*reinterpret_cast<__half2*>(&u2.x)); a2.x += f.x; a2.y += f.y;
        f = __half22float2(*reinterpret_cast<__half2*>(&u2.y)); a2.z += f.x; a2.w += f.y;
        f = __half22float2(*reinterpret_cast<__half2*>(&u3.x)); a3.x += f.x; a3.y += f.y;
        f = __half22float2(*reinterpret_cast<__half2*>(&u3.y)); a3.z += f.x; a3.w += f.y;
    }
    for (; p < e; p++) {
        int i0 = g_srcsorted[p];
        uint2 u0 = *reinterpret_cast<const uint2*>(&g_nh[(size_t)i0 * 128 + lane * 4]);
        float2 f;
        f = __half22float2(*reinterpret_cast<__half2*>(&u0.x)); a0.x += f.x; a0.y += f.y;
        f = __half22float2(*reinterpret_cast<__half2*>(&u0.y)); a0.z += f.x; a0.w += f.y;
    }
    a0.x += a1.x; a0.y += a1.y; a0.z += a1.z; a0.w += a1.w;
    a2.x += a3.x; a2.y += a3.y; a2.z += a3.z; a2.w += a3.w;
    a0.x += a2.x; a0.y += a2.y; a0.z += a2.z; a0.w += a2.w;

    xr.x += EPS * tanh_fast(cv.x + a0.x + bv.x);
    xr.y += EPS * tanh_fast(cv.y + a0.y + bv.y);
    xr.z += EPS * tanh_fast(cv.z + a0.z + bv.z);
    xr.w += EPS * tanh_fast(cv.w + a0.w + bv.w);
    *reinterpret_cast<float4*>(&g_x[(size_t)node * HH + lane * 4]) = xr;

    __half2 h0 = __floats2half2_rn(xr.x, xr.y);
    __half2 h1 = __floats2half2_rn(xr.z, xr.w);
    *reinterpret_cast<uint2*>(&g_xh[(size_t)node * HH + lane * 4]) =
        make_uint2(*reinterpret_cast<uint32_t*>(&h0), *reinterpret_cast<uint32_t*>(&h1));
}

// ---------------- pooling ----------------
__global__ void gstart_kernel(const int* __restrict__ batch) {
    int g = blockIdx.x * blockDim.x + threadIdx.x;
    if (g > GG) return;
    int lo = 0, hi = NN;
    while (lo < hi) {
        int mid = (lo + hi) >> 1;
        if (batch[mid] < g) lo = mid + 1; else hi = mid;
    }
    g_gstart[g] = lo;
}

__global__ void pool_kernel() {
    int g = blockIdx.x;
    int c = threadIdx.x;
    int s = g_gstart[g], e = g_gstart[g + 1];
    float sum = 0.f;
    float mx = -3.402823466e+38f;
    for (int i = s; i < e; i++) {
        float v = g_x[(size_t)i * HH + c];
        sum += v;
        mx = fmaxf(mx, v);
    }
    int cnt = e - s;
    g_pooled[g * 384 + c] = sum;
    g_pooled[g * 384 + 128 + c] = (cnt > 0) ? mx : 0.f;
    g_pooled[g * 384 + 256 + c] = sum / fmaxf((float)cnt, 1.0f);
}

// ---------------- MLP head ----------------
__global__ void mlp1_kernel(const float* __restrict__ l1w, const float* __restrict__ l1b) {
    __shared__ float prow[384];
    int g = blockIdx.x;
    int j = threadIdx.x;
    for (int idx = j; idx < 384; idx += 192) prow[idx] = g_pooled[g * 384 + idx];
    __syncthreads();
    float acc = l1b[j];
    const float* wrow = &l1w[j * 384];
    #pragma unroll 8
    for (int k = 0; k < 384; k++) acc += prow[k] * wrow[k];
    g_h[g * 192 + j] = (acc > 0.f) ? acc : SLOPE * acc;
}

__global__ void mlp2_kernel(const float* __restrict__ l2w, const float* __restrict__ l2b,
                            float* __restrict__ out) {
    __shared__ float hrow[192];
    int g = blockIdx.x;
    int j = threadIdx.x;
    for (int idx = j; idx < 192; idx += 64) hrow[idx] = g_h[g * 192 + idx];
    __syncthreads();
    float acc = l2b[j];
    const float* wrow = &l2w[j * 192];
    #pragma unroll 8
    for (int k = 0; k < 192; k++) acc += hrow[k] * wrow[k];
    out[g * OUTD + j] = (acc > 0.f) ? acc : SLOPE * acc;
}

// ---------------- launch ----------------
extern "C" void kernel_launch(void* const* d_in, const int* in_sizes, int n_in,
                              void* d_out, int out_size) {
    const float* x_in  = (const float*)d_in[0];
    const int*   ei    = (const int*)d_in[1];
    const int*   batch = (const int*)d_in[2];
    const float* W     = (const float*)d_in[3];
    const float* bias  = (const float*)d_in[4];
    const float* lin_w = (const float*)d_in[5];
    const float* l1w   = (const float*)d_in[6];
    const float* l1b   = (const float*)d_in[7];
    const float* l2w   = (const float*)d_in[8];
    const float* l2b   = (const float*)d_in[9];
    float* out = (float*)d_out;

    cudaFuncSetAttribute(gemm_hmma_kernel, cudaFuncAttributeMaxDynamicSharedMemorySize, SM_TOTAL);

    dim3 ggrid((NN + 127) / 128, 2);

    // prep (gemm#1 is launch #4 -> profiled)
    wprep_kernel<<<256, 128>>>(W, lin_w);
    copy_x_kernel<<<(NN * HH / 4 + 255) / 256, 256>>>(x_in);
    hist_kernel<<<(EE + 255) / 256, 256>>>(ei);
    gemm_hmma_kernel<<<ggrid, 256, SM_TOTAL>>>();
    scan_local_kernel<<<SCAN_NBLK, 512>>>();
    scan_tops_kernel<<<1, 128>>>();
    scan_add_kernel<<<SCAN_NBLK, 512>>>();
    fill_kernel<<<(EE + 255) / 256, 256>>>(ei);
    agg_update_kernel<<<(NN * 32 + 255) / 256, 256>>>(bias);

    for (int it = 1; it < NITER; it++) {
        gemm_hmma_kernel<<<ggrid, 256, SM_TOTAL>>>();
        agg_update_kernel<<<(NN * 32 + 255) / 256, 256>>>(bias);
    }

    gstart_kernel<<<1, 512>>>(batch);
    pool_kernel<<<GG, HH>>>();
    mlp1_kernel<<<GG, 192>>>(l1w, l1b);
    mlp2_kernel<<<GG, OUTD>>>(l2w, l2b, out);
}

// round 16
// speedup vs baseline: 1.0780x; 1.0401x over previous
#include <cuda_runtime.h>
#include <cuda_fp16.h>
#include <cstdint>
#include <math.h>

#define NN 50000
#define HH 128
#define EE 600000
#define GG 256
#define OUTD 64
#define NITER 5
#define GAMMA 0.1f
#define EPS 0.1f
#define SLOPE 0.01f
#define SCAN_NBLK 98   /* ceil(50000/512) */

// ---------------- device scratch (static, allocation-free) ----------------
__device__ float g_x[NN * HH];
__device__ __half g_xh[NN * HH];               // fp16 x (GEMM A operand)
__device__ __half g_nh[NN * HH];               // neigh, fp16 (gathered)
__device__ __half g_ch[NN * HH];               // conv_lin, fp16
__device__ __half g_Wh[256 * 128];
__device__ int   g_counts[NN];
__device__ int   g_rowptr[NN + 1];
__device__ int   g_fillptr[NN];
__device__ int   g_blocksums[SCAN_NBLK];
__device__ int   g_srcsorted[EE];
__device__ int   g_gstart[GG + 1];
__device__ float g_pooled[GG * 384];
__device__ float g_h[GG * 192];

__device__ __forceinline__ uint32_t smem_u32(const void* p) {
    uint32_t a;
    asm("{ .reg .u64 t; cvta.to.shared.u64 t, %1; cvt.u32.u64 %0, t; }" : "=r"(a) : "l"(p));
    return a;
}

__device__ __forceinline__ float tanh_fast(float x) {
    float r;
    asm("tanh.approx.f32 %0, %1;" : "=f"(r) : "f"(x));
    return r;
}

// ---------------- prep kernels ----------------
// W2 fp16 prep + zero histogram counts (fused; grid covers 50048 threads)
__global__ void wprep_zero_kernel(const float* __restrict__ W, const float* __restrict__ lin_w) {
    int t = blockIdx.x * blockDim.x + threadIdx.x;
    if (t < 256 * 128) {
        int n = t >> 7;
        int k = t & 127;
        float v;
        if (n < 128) {
            v = lin_w[n * HH + k];
        } else {
            int np = n - 128;
            v = W[np * HH + k] - W[k * HH + np] - (np == k ? GAMMA : 0.0f);
        }
        g_Wh[n * 128 + k] = __float2half_rn(v);
    }
    if (t < NN) g_counts[t] = 0;
}

// copy x + fp16 convert + edge histogram (fused; counts zeroed in previous launch)
__global__ void copyx_hist_kernel(const float* __restrict__ xin, const int* __restrict__ ei) {
    int i = blockIdx.x * blockDim.x + threadIdx.x;
    if (i < EE) {
        int dst = ei[EE + i];
        atomicAdd(&g_counts[dst], 1);
    }
    if (i < NN * HH / 4) {
        float4 f = reinterpret_cast<const float4*>(xin)[i];
        reinterpret_cast<float4*>(g_x)[i] = f;
        __half2 h0 = __floats2half2_rn(f.x, f.y);
        __half2 h1 = __floats2half2_rn(f.z, f.w);
        reinterpret_cast<uint2*>(g_xh)[i] =
            make_uint2(*reinterpret_cast<uint32_t*>(&h0), *reinterpret_cast<uint32_t*>(&h1));
    }
}

// ---- multi-block scan, 3 phases ----
__global__ void scan_local_kernel() {
    __shared__ int ws[16];
    int i = blockIdx.x * 512 + threadIdx.x;
    int lane = threadIdx.x & 31;
    int wid = threadIdx.x >> 5;
    int v = (i < NN) ? g_counts[i] : 0;
    int inc = v;
    #pragma unroll
    for (int off = 1; off < 32; off <<= 1) {
        int o = __shfl_up_sync(0xffffffffu, inc, off);
        if (lane >= off) inc += o;
    }
    if (lane == 31) ws[wid] = inc;
    __syncthreads();
    if (wid == 0) {
        int w = (lane < 16) ? ws[lane] : 0;
        int wi = w;
        #pragma unroll
        for (int off = 1; off < 32; off <<= 1) {
            int o = __shfl_up_sync(0xffffffffu, wi, off);
            if (lane >= off) wi += o;
        }
        if (lane < 16) ws[lane] = wi - w;
    }
    __syncthreads();
    int exc = ws[wid] + inc - v;
    if (i < NN) g_rowptr[i] = exc;
    if (threadIdx.x == 511) g_blocksums[blockIdx.x] = exc + v;
}

__global__ void scan_tops_kernel() {
    __shared__ int ws[4];
    int t = threadIdx.x;
    int lane = t & 31;
    int wid = t >> 5;
    int v = (t < SCAN_NBLK) ? g_blocksums[t] : 0;
    int inc = v;
    #pragma unroll
    for (int off = 1; off < 32; off <<= 1) {
        int o = __shfl_up_sync(0xffffffffu, inc, off);
        if (lane >= off) inc += o;
    }
    if (lane == 31) ws[wid] = inc;
    __syncthreads();
    if (t == 0) {
        int r = 0;
        #pragma unroll
        for (int q = 0; q < 4; q++) { int x = ws[q]; ws[q] = r; r += x; }
    }
    __syncthreads();
    if (t < SCAN_NBLK) g_blocksums[t] = ws[wid] + inc - v;
}

__global__ void scan_add_kernel() {
    int i = blockIdx.x * 512 + threadIdx.x;
    if (i < NN) {
        int r = g_rowptr[i] + g_blocksums[blockIdx.x];
        g_rowptr[i] = r;
        g_fillptr[i] = r;
    }
    if (i == 0) g_rowptr[NN] = EE;
}

__global__ void fill_kernel(const int* __restrict__ ei) {
    int e = blockIdx.x * blockDim.x + threadIdx.x;
    if (e < EE) {
        int src = ei[e];
        int dst = ei[EE + e];
        int pos = atomicAdd(&g_fillptr[dst], 1);
        g_srcsorted[pos] = src;
    }
}

// ---------------- HMMA GEMM (pure fp16, 1-term, M128xN128, warp 32x64) ----------------
#define SROWB 272
#define OFF_A 0
#define OFF_B 34816                  // 128*272
#define SM_TOTAL 69632               // + 128*272

#define LDM_X4(d, addr) \
    asm volatile("ldmatrix.sync.aligned.m8n8.x4.shared.b16 {%0,%1,%2,%3}, [%4];" \
        : "=r"((d)[0]), "=r"((d)[1]), "=r"((d)[2]), "=r"((d)[3]) : "r"(addr))

#define MMA_F16(c, a, b) \
    asm volatile("mma.sync.aligned.m16n8k16.row.col.f32.f16.f16.f32 " \
        "{%0,%1,%2,%3}, {%4,%5,%6,%7}, {%8,%9}, {%0,%1,%2,%3};" \
        : "+f"((c)[0]), "+f"((c)[1]), "+f"((c)[2]), "+f"((c)[3]) \
        : "r"((a)[0]), "r"((a)[1]), "r"((a)[2]), "r"((a)[3]), "r"((b)[0]), "r"((b)[1]))

__device__ __forceinline__ void cp16(uint32_t dst, const void* src, uint32_t srcsize) {
    asm volatile("cp.async.ca.shared.global [%0], [%1], 16, %2;"
                 :: "r"(dst), "l"(src), "r"(srcsize) : "memory");
}

__global__ __launch_bounds__(256, 2) void gemm_hmma_kernel() {
    extern __shared__ char sm[];
    uint32_t sb = smem_u32(sm);
    int tid = threadIdx.x;
    int warp = tid >> 5;
    int lane = tid & 31;
    int rowbase = blockIdx.x * 128;
    int nbase = blockIdx.y * 128;

    #pragma unroll
    for (int h = 0; h < 2; h++) {
        #pragma unroll
        for (int p = 0; p < 4; p++) {
            int idx = tid + p * 256;
            int row = idx >> 3;
            int cc = (idx & 7) + h * 8;
            int gr = rowbase + row;
            uint32_t ok = (gr < NN) ? 16u : 0u;
            int grc = (gr < NN) ? gr : 0;
            uint32_t doff = (uint32_t)(row * SROWB + cc * 16);
            cp16(sb + OFF_A + doff, &g_xh[(size_t)grc * 128 + cc * 8], ok);
        }
        #pragma unroll
        for (int p = 0; p < 4; p++) {
            int idx = tid + p * 256;
            int row = idx >> 3;
            int cc = (idx & 7) + h * 8;
            uint32_t doff = (uint32_t)(row * SROWB + cc * 16);
            cp16(sb + OFF_B + doff, &g_Wh[(size_t)(nbase + row) * 128 + cc * 8], 16u);
        }
        asm volatile("cp.async.commit_group;");
    }

    int mrow = (warp & 3) * 32;
    int ncol = (warp >> 2) * 64;
    int g = lane >> 2;
    int tig = lane & 3;

    uint32_t aoffA = (uint32_t)((mrow + (lane & 15)) * SROWB + (lane >> 4) * 16);
    int bm = lane >> 3;
    uint32_t aoffB = (uint32_t)((ncol + ((bm >> 1) << 3) + (lane & 7)) * SROWB + (bm & 1) * 16);

    float acc[2][8][4];
    #pragma unroll
    for (int mt = 0; mt < 2; mt++)
        #pragma unroll
        for (int nt = 0; nt < 8; nt++)
            #pragma unroll
            for (int q = 0; q < 4; q++) acc[mt][nt][q] = 0.f;

    asm volatile("cp.async.wait_group 1;");
    __syncthreads();

    #pragma unroll
    for (int ks = 0; ks < 8; ks++) {
        if (ks == 4) {
            asm volatile("cp.async.wait_group 0;");
            __syncthreads();
        }
        uint32_t kb = (uint32_t)(ks * 32);
        uint32_t aa[2][4], bb[4][4];
        #pragma unroll
        for (int mt = 0; mt < 2; mt++) {
            LDM_X4(aa[mt], sb + OFF_A + aoffA + mt * 16 * SROWB + kb);
        }
        #pragma unroll
        for (int pr = 0; pr < 4; pr++) {
            LDM_X4(bb[pr], sb + OFF_B + aoffB + pr * 16 * SROWB + kb);
        }
        #pragma unroll
        for (int mt = 0; mt < 2; mt++) {
            #pragma unroll
            for (int nt = 0; nt < 8; nt++) {
                uint32_t bh[2] = {bb[nt >> 1][(nt & 1) * 2], bb[nt >> 1][(nt & 1) * 2 + 1]};
                MMA_F16(acc[mt][nt], aa[mt], bh);
            }
        }
    }

    // epilogue: both halves stored fp16 (neigh -> g_nh, conv -> g_ch)
    __half* dst = (blockIdx.y == 0) ? g_nh : g_ch;
    #pragma unroll
    for (int mt = 0; mt < 2; mt++) {
        int r0 = rowbase + mrow + mt * 16 + g;
        int r1 = r0 + 8;
        #pragma unroll
        for (int nt = 0; nt < 8; nt++) {
            int col = ncol + nt * 8 + 2 * tig;
            __half2 p0 = __floats2half2_rn(acc[mt][nt][0], acc[mt][nt][1]);
            __half2 p1 = __floats2half2_rn(acc[mt][nt][2], acc[mt][nt][3]);
            if (r0 < NN) *reinterpret_cast<__half2*>(&dst[(size_t)r0 * 128 + col]) = p0;
            if (r1 < NN) *reinterpret_cast<__half2*>(&dst[(size_t)r1 * 128 + col]) = p1;
        }
    }
}

// ---------------- fused aggregate + conv + tanh + x update (warp per node) ----------------
__global__ __launch_bounds__(256) void agg_update_kernel(const float* __restrict__ bias) {
    int node = (blockIdx.x * blockDim.x + threadIdx.x) >> 5;
    int lane = threadIdx.x & 31;
    if (node >= NN) return;
    int s = g_rowptr[node];
    int e = g_rowptr[node + 1];

    uint2 cvu = *reinterpret_cast<const uint2*>(&g_ch[(size_t)node * 128 + lane * 4]);
    float4 xr = *reinterpret_cast<const float4*>(&g_x[(size_t)node * HH + lane * 4]);
    float4 bv = *reinterpret_cast<const float4*>(&bias[lane * 4]);
    float2 c0 = __half22float2(*reinterpret_cast<__half2*>(&cvu.x));
    float2 c1 = __half22float2(*reinterpret_cast<__half2*>(&cvu.y));

    float4 a0 = make_float4(0.f, 0.f, 0.f, 0.f);
    float4 a1 = a0, a2 = a0, a3 = a0;

    int p = s;
    for (; p + 3 < e; p += 4) {
        int i0 = g_srcsorted[p + 0];
        int i1 = g_srcsorted[p + 1];
        int i2 = g_srcsorted[p + 2];
        int i3 = g_srcsorted[p + 3];
        uint2 u0 = *reinterpret_cast<const uint2*>(&g_nh[(size_t)i0 * 128 + lane * 4]);
        uint2 u1 = *reinterpret_cast<const uint2*>(&g_nh[(size_t)i1 * 128 + lane * 4]);
        uint2 u2 = *reinterpret_cast<const uint2*>(&g_nh[(size_t)i2 * 128 + lane * 4]);
        uint2 u3 = *reinterpret_cast<const uint2*>(&g_nh[(size_t)i3 * 128 + lane * 4]);
        float2 f;
        f = __half22float2(*reinterpret_cast<__half2*>(&u0.x)); a0.x += f.x; a0.y += f.y;
        f = __half22float2(*reinterpret_cast<__half2*>(&u0.y)); a0.z += f.x; a0.w += f.y;
        f = __half22float2(*reinterpret_cast<__half2*>(&u1.x)); a1.x += f.x; a1.y += f.y;
        f = __half22float2(*reinterpret_cast<__half2*>(&u1.y)); a1.z += f.x; a1.w += f.y;
        f = __half22float2(*reinterpret_cast<__half2*>(&u2.x)); a2.x += f.x; a2.y += f.y;
        f = __half22float2(*reinterpret_cast<__half2*>(&u2.y)); a2.z += f.x; a2.w += f.y;
        f = __half22float2(*reinterpret_cast<__half2*>(&u3.x)); a3.x += f.x; a3.y += f.y;
        f = __half22float2(*reinterpret_cast<__half2*>(&u3.y)); a3.z += f.x; a3.w += f.y;
    }
    for (; p < e; p++) {
        int i0 = g_srcsorted[p];
        uint2 u0 = *reinterpret_cast<const uint2*>(&g_nh[(size_t)i0 * 128 + lane * 4]);
        float2 f;
        f = __half22float2(*reinterpret_cast<__half2*>(&u0.x)); a0.x += f.x; a0.y += f.y;
        f = __half22float2(*reinterpret_cast<__half2*>(&u0.y)); a0.z += f.x; a0.w += f.y;
    }
    a0.x += a1.x; a0.y += a1.y; a0.z += a1.z; a0.w += a1.w;
    a2.x += a3.x; a2.y += a3.y; a2.z += a3.z; a2.w += a3.w;
    a0.x += a2.x; a0.y += a2.y; a0.z += a2.z; a0.w += a2.w;

    xr.x += EPS * tanh_fast(c0.x + a0.x + bv.x);
    xr.y += EPS * tanh_fast(c0.y + a0.y + bv.y);
    xr.z += EPS * tanh_fast(c1.x + a0.z + bv.z);
    xr.w += EPS * tanh_fast(c1.y + a0.w + bv.w);
    *reinterpret_cast<float4*>(&g_x[(size_t)node * HH + lane * 4]) = xr;

    __half2 h0 = __floats2half2_rn(xr.x, xr.y);
    __half2 h1 = __floats2half2_rn(xr.z, xr.w);
    *reinterpret_cast<uint2*>(&g_xh[(size_t)node * HH + lane * 4]) =
        make_uint2(*reinterpret_cast<uint32_t*>(&h0), *reinterpret_cast<uint32_t*>(&h1));
}

// ---------------- pooling ----------------
__global__ void gstart_kernel(const int* __restrict__ batch) {
    int g = blockIdx.x * blockDim.x + threadIdx.x;
    if (g > GG) return;
    int lo = 0, hi = NN;
    while (lo < hi) {
        int mid = (lo + hi) >> 1;
        if (batch[mid] < g) lo = mid + 1; else hi = mid;
    }
    g_gstart[g] = lo;
}

__global__ void pool_kernel() {
    int g = blockIdx.x;
    int c = threadIdx.x;
    int s = g_gstart[g], e = g_gstart[g + 1];
    float sum0 = 0.f, sum1 = 0.f;
    float mx0 = -3.402823466e+38f, mx1 = -3.402823466e+38f;
    int i = s;
    for (; i + 1 < e; i += 2) {
        float v0 = g_x[(size_t)i * HH + c];
        float v1 = g_x[(size_t)(i + 1) * HH + c];
        sum0 += v0; mx0 = fmaxf(mx0, v0);
        sum1 += v1; mx1 = fmaxf(mx1, v1);
    }
    if (i < e) {
        float v0 = g_x[(size_t)i * HH + c];
        sum0 += v0; mx0 = fmaxf(mx0, v0);
    }
    float sum = sum0 + sum1;
    float mx = fmaxf(mx0, mx1);
    int cnt = e - s;
    g_pooled[g * 384 + c] = sum;
    g_pooled[g * 384 + 128 + c] = (cnt > 0) ? mx : 0.f;
    g_pooled[g * 384 + 256 + c] = sum / fmaxf((float)cnt, 1.0f);
}

// ---------------- MLP head ----------------
__global__ void mlp1_kernel(const float* __restrict__ l1w, const float* __restrict__ l1b) {
    __shared__ float prow[384];
    int g = blockIdx.x;
    int j = threadIdx.x;
    for (int idx = j; idx < 384; idx += 192) prow[idx] = g_pooled[g * 384 + idx];
    __syncthreads();
    float acc = l1b[j];
    const float* wrow = &l1w[j * 384];
    #pragma unroll 8
    for (int k = 0; k < 384; k++) acc += prow[k] * wrow[k];
    g_h[g * 192 + j] = (acc > 0.f) ? acc : SLOPE * acc;
}

__global__ void mlp2_kernel(const float* __restrict__ l2w, const float* __restrict__ l2b,
                            float* __restrict__ out) {
    __shared__ float hrow[192];
    int g = blockIdx.x;
    int j = threadIdx.x;
    for (int idx = j; idx < 192; idx += 64) hrow[idx] = g_h[g * 192 + idx];
    __syncthreads();
    float acc = l2b[j];
    const float* wrow = &l2w[j * 192];
    #pragma unroll 8
    for (int k = 0; k < 192; k++) acc += hrow[k] * wrow[k];
    out[g * OUTD + j] = (acc > 0.f) ? acc : SLOPE * acc;
}

// ---------------- launch ----------------
extern "C" void kernel_launch(void* const* d_in, const int* in_sizes, int n_in,
                              void* d_out, int out_size) {
    const float* x_in  = (const float*)d_in[0];
    const int*   ei    = (const int*)d_in[1];
    const int*   batch = (const int*)d_in[2];
    const float* W     = (const float*)d_in[3];
    const float* bias  = (const float*)d_in[4];
    const float* lin_w = (const float*)d_in[5];
    const float* l1w   = (const float*)d_in[6];
    const float* l1b   = (const float*)d_in[7];
    const float* l2w   = (const float*)d_in[8];
    const float* l2b   = (const float*)d_in[9];
    float* out = (float*)d_out;

    cudaFuncSetAttribute(gemm_hmma_kernel, cudaFuncAttributeMaxDynamicSharedMemorySize, SM_TOTAL);

    dim3 ggrid((NN + 127) / 128, 2);

    // prep (gemm#1 stays launch #4 -> profiled)
    wprep_zero_kernel<<<(NN + 255) / 256, 256>>>(W, lin_w);              // W prep + zero counts
    copyx_hist_kernel<<<(NN * HH / 4 + 255) / 256, 256>>>(x_in, ei);     // x copy/convert + hist
    scan_local_kernel<<<SCAN_NBLK, 512>>>();
    gemm_hmma_kernel<<<ggrid, 256, SM_TOTAL>>>();                        // launch #4 (profiled)
    scan_tops_kernel<<<1, 128>>>();
    scan_add_kernel<<<SCAN_NBLK, 512>>>();
    fill_kernel<<<(EE + 255) / 256, 256>>>(ei);
    agg_update_kernel<<<(NN * 32 + 255) / 256, 256>>>(bias);

    for (int it = 1; it < NITER; it++) {
        gemm_hmma_kernel<<<ggrid, 256, SM_TOTAL>>>();
        agg_update_kernel<<<(NN * 32 + 255) / 256, 256>>>(bias);
    }

    gstart_kernel<<<1, 512>>>(batch);
    pool_kernel<<<GG, HH>>>();
    mlp1_kernel<<<GG, 192>>>(l1w, l1b);
    mlp2_kernel<<<GG, OUTD>>>(l2w, l2b, out);
}